// round 11
// baseline (speedup 1.0000x reference)
#include <cuda_runtime.h>

#define IMG 512
#define BATCH 32
#define TW 128
#define TH 16
#define RAD 5
#define RAW_W 138        // TW + 2*RAD columns needed by stage 2
#define RS 140           // vbuf row stride (floats), multiple of 4 for float4 LDS
#define NTHREADS 288
#define NWARPS (NTHREADS / 32)
#define NBLOCKS 4096     // (512/128) * (512/16) * 32
#define NPIX_D 8388608.0
#define G 4              // stage-1 vertical row-group size
#define NSLOTS1 (4 * RAW_W)   // 552 stage-1 slots: 552/288 -> max 2/thread
#define NSLOTS2 (TW * TH / 4) // 512 stage-2 slots
#define JROWS (G + 10)        // 14 raw rows feed 4 output rows

__device__ double g_accum;          // zero-initialized at module load
__device__ unsigned int g_count;    // zero-initialized at module load

// Normalized 1-D Gaussian, sigma=1.5, K=11; symmetric W[d]=W[10-d]
__device__ __forceinline__ float wgt(int d) {
    const float WH[6] = {0.00102838f, 0.00759876f, 0.03600078f,
                         0.10936070f, 0.21300554f, 0.26601172f};
    return WH[d < 6 ? d : 10 - d];
}

__global__ __launch_bounds__(NTHREADS, 5)
void ssim_main_kernel(const float* __restrict__ img1, const float* __restrict__ img2,
                      float* __restrict__ out) {
    extern __shared__ float sm[];
    float* vbuf = sm;                   // 5 planes * 16 * 140
    float* red  = sm + 5 * TH * RS;     // NWARPS floats

    const int tid = threadIdx.x;
    const int bx0 = blockIdx.x * TW - RAD;
    const int by0 = blockIdx.y * TH - RAD;
    const long ib = (long)blockIdx.z * IMG * IMG;

    // ---- stage 1: vertical 11-tap conv of 5 quantities, direct from global ----
    // 552 slots = 138 columns x 4 row-groups; 288 threads -> at most 2 slots each.
    for (int s = tid; s < NSLOTS1; s += NTHREADS) {
        int grp = s / RAW_W;                // constant division -> mul/shift
        int col = s - grp * RAW_W;          // 0..137
        int ybase = grp * G;
        int gx = bx0 + col;
        int gybase = by0 + ybase;
        const bool xin = (gx >= 0) & (gx < IMG);
        const float* p1 = img1 + ib + (long)gybase * IMG + gx;
        const float* p2 = img2 + ib + (long)gybase * IMG + gx;

        float acc0[G] = {0,0,0,0};
        float acc1[G] = {0,0,0,0};
        float acc2[G] = {0,0,0,0};
        float acc3[G] = {0,0,0,0};
        float acc4[G] = {0,0,0,0};
        #pragma unroll
        for (int j = 0; j < JROWS; j++) {
            int gy = gybase + j;
            bool in = xin & (gy >= 0) & (gy < IMG);
            float av = in ? p1[j * IMG] : 0.f;   // immediate offsets off base reg
            float bv = in ? p2[j * IMG] : 0.f;
            float aa = av * av, bb = bv * bv, ab = av * bv;
            #pragma unroll
            for (int o = 0; o < G; o++) {
                const int d = j - o;
                if (d >= 0 && d < 11) {
                    const float w = wgt(d);      // compile-time const -> FFMA-imm
                    acc0[o] += w * av;
                    acc1[o] += w * bv;
                    acc2[o] += w * aa;
                    acc3[o] += w * bb;
                    acc4[o] += w * ab;
                }
            }
        }
        #pragma unroll
        for (int o = 0; o < G; o++) {
            int row = ybase + o;
            vbuf[(0 * TH + row) * RS + col] = acc0[o];
            vbuf[(1 * TH + row) * RS + col] = acc1[o];
            vbuf[(2 * TH + row) * RS + col] = acc2[o];
            vbuf[(3 * TH + row) * RS + col] = acc3[o];
            vbuf[(4 * TH + row) * RS + col] = acc4[o];
        }
    }
    __syncthreads();

    // ---- stage 2: horizontal 11-tap conv (float4 window loads) + SSIM ----
    float lsum = 0.f;
    for (int slot = tid; slot < NSLOTS2; slot += NTHREADS) {
        int xg = slot & 31;                 // 32 x-groups * 16 rows
        int y  = slot >> 5;
        int x0 = xg * 4;                    // 16B-aligned (RS multiple of 4)
        float res[5][4];
        #pragma unroll
        for (int q = 0; q < 5; q++) {
            const float* row = vbuf + (q * TH + y) * RS + x0;
            float win[14];
            float4 v0 = *(const float4*)(row);
            float4 v1 = *(const float4*)(row + 4);
            float4 v2 = *(const float4*)(row + 8);
            float2 v3 = *(const float2*)(row + 12);
            win[0] = v0.x;  win[1] = v0.y;  win[2]  = v0.z;  win[3]  = v0.w;
            win[4] = v1.x;  win[5] = v1.y;  win[6]  = v1.z;  win[7]  = v1.w;
            win[8] = v2.x;  win[9] = v2.y;  win[10] = v2.z;  win[11] = v2.w;
            win[12] = v3.x; win[13] = v3.y;
            #pragma unroll
            for (int o = 0; o < 4; o++) {
                float sacc = 0.f;
                #pragma unroll
                for (int d = 0; d < 11; d++) sacc += wgt(d) * win[o + d];
                res[q][o] = sacc;
            }
        }
        #pragma unroll
        for (int o = 0; o < 4; o++) {
            float mu1 = res[0][o], mu2 = res[1][o];
            float mu1sq = mu1 * mu1, mu2sq = mu2 * mu2, mu12 = mu1 * mu2;
            float s1  = res[2][o] - mu1sq;
            float s2  = res[3][o] - mu2sq;
            float s12 = res[4][o] - mu12;
            float num = (2.f * mu12 + 0.0001f) * (2.f * s12 + 0.0009f);
            float den = (mu1sq + mu2sq + 0.0001f) * (s1 + s2 + 0.0009f);
            lsum += __fdividef(num, den);
        }
    }

    // ---- block reduction (9 warps) ----
    #pragma unroll
    for (int off = 16; off > 0; off >>= 1)
        lsum += __shfl_xor_sync(0xffffffff, lsum, off);
    if ((tid & 31) == 0) red[tid >> 5] = lsum;
    __syncthreads();

    // ---- single-kernel finalize: atomic accumulate + last-block writes out ----
    if (tid == 0) {
        float v = 0.f;
        #pragma unroll
        for (int w = 0; w < NWARPS; w++) v += red[w];
        atomicAdd(&g_accum, (double)v);
        __threadfence();
        unsigned int ticket = atomicAdd(&g_count, 1u);
        if (ticket == NBLOCKS - 1) {
            double sfin = atomicAdd(&g_accum, 0.0);   // coherent read of final sum
            out[0] = (float)(1.0 - sfin / NPIX_D);
            g_accum = 0.0;                             // reset for next graph replay
            g_count = 0u;
        }
    }
}

extern "C" void kernel_launch(void* const* d_in, const int* in_sizes, int n_in,
                              void* d_out, int out_size) {
    const float* img1 = (const float*)d_in[0];
    const float* img2 = (const float*)d_in[1];
    float* out = (float*)d_out;

    const size_t smem = (size_t)(5 * TH * RS + NWARPS) * sizeof(float);  // ~44.9 KB
    cudaFuncSetAttribute(ssim_main_kernel,
                         cudaFuncAttributeMaxDynamicSharedMemorySize, (int)smem);

    dim3 grid(IMG / TW, IMG / TH, BATCH);   // 4 x 32 x 32 = 4096 blocks
    ssim_main_kernel<<<grid, NTHREADS, smem>>>(img1, img2, out);
}

// round 13
// speedup vs baseline: 1.6449x; 1.6449x over previous
#include <cuda_runtime.h>

#define IMG 512
#define BATCH 32
#define TW 128
#define TH 16
#define RAD 5
#define RAW_W 138        // TW + 2*RAD columns needed by stage 2
#define RS 140           // vbuf row stride (floats), multiple of 4 for float4 LDS
#define NTHREADS 288
#define NWARPS (NTHREADS / 32)
#define NBLOCKS 4096     // (512/128) * (512/16) * 32
#define NPIX_D 8388608.0
#define G 4              // stage-1 vertical row-group size
#define NSLOTS1 (4 * RAW_W)   // 552 stage-1 slots: 552/288 -> max 2/thread
#define NSLOTS2 (TW * TH / 4) // 512 stage-2 slots: tid and tid+288 (guarded)
#define JROWS (G + 10)        // 14 raw rows feed 4 output rows

__device__ double g_accum;          // zero-initialized at module load
__device__ unsigned int g_count;    // zero-initialized at module load

// Normalized 1-D Gaussian, sigma=1.5, K=11; symmetric W[d]=W[10-d]
__device__ __forceinline__ float wgt(int d) {
    const float WH[6] = {0.00102838f, 0.00759876f, 0.03600078f,
                         0.10936070f, 0.21300554f, 0.26601172f};
    return WH[d < 6 ? d : 10 - d];
}

// One stage-2 slot: horizontal 11-tap conv of 5 planes + SSIM for 4 pixels.
// All locals scalar after forced unroll -> register resident.
__device__ __forceinline__ float stage2_slot(const float* __restrict__ vbuf, int slot) {
    const int xg = slot & 31;               // 32 x-groups * 16 rows
    const int y  = slot >> 5;
    const int x0 = xg * 4;                  // 16B-aligned (RS multiple of 4)
    float res[5][4];
    #pragma unroll
    for (int q = 0; q < 5; q++) {
        const float* row = vbuf + (q * TH + y) * RS + x0;
        float win[14];
        float4 v0 = *(const float4*)(row);
        float4 v1 = *(const float4*)(row + 4);
        float4 v2 = *(const float4*)(row + 8);
        float2 v3 = *(const float2*)(row + 12);
        win[0] = v0.x;  win[1] = v0.y;  win[2]  = v0.z;  win[3]  = v0.w;
        win[4] = v1.x;  win[5] = v1.y;  win[6]  = v1.z;  win[7]  = v1.w;
        win[8] = v2.x;  win[9] = v2.y;  win[10] = v2.z;  win[11] = v2.w;
        win[12] = v3.x; win[13] = v3.y;
        #pragma unroll
        for (int o = 0; o < 4; o++) {
            float sacc = 0.f;
            #pragma unroll
            for (int d = 0; d < 11; d++) sacc += wgt(d) * win[o + d];
            res[q][o] = sacc;
        }
    }
    float acc = 0.f;
    #pragma unroll
    for (int o = 0; o < 4; o++) {
        float mu1 = res[0][o], mu2 = res[1][o];
        float mu1sq = mu1 * mu1, mu2sq = mu2 * mu2, mu12 = mu1 * mu2;
        float s1  = res[2][o] - mu1sq;
        float s2  = res[3][o] - mu2sq;
        float s12 = res[4][o] - mu12;
        float num = (2.f * mu12 + 0.0001f) * (2.f * s12 + 0.0009f);
        float den = (mu1sq + mu2sq + 0.0001f) * (s1 + s2 + 0.0009f);
        acc += __fdividef(num, den);
    }
    return acc;
}

__global__ __launch_bounds__(NTHREADS, 4)
void ssim_main_kernel(const float* __restrict__ img1, const float* __restrict__ img2,
                      float* __restrict__ out) {
    extern __shared__ float sm[];
    float* vbuf = sm;                   // 5 planes * 16 * 140
    float* red  = sm + 5 * TH * RS;     // NWARPS floats

    const int tid = threadIdx.x;
    const int bx0 = blockIdx.x * TW - RAD;
    const int by0 = blockIdx.y * TH - RAD;
    const long ib = (long)blockIdx.z * IMG * IMG;

    // ---- stage 1: vertical 11-tap conv of 5 quantities, direct from global ----
    // 552 slots = 138 columns x 4 row-groups; 288 threads -> at most 2 slots each.
    for (int s = tid; s < NSLOTS1; s += NTHREADS) {
        int grp = s / RAW_W;                // constant division -> mul/shift
        int col = s - grp * RAW_W;          // 0..137
        int ybase = grp * G;
        int gx = bx0 + col;
        int gybase = by0 + ybase;
        const bool xin = (gx >= 0) & (gx < IMG);
        const float* p1 = img1 + ib + (long)gybase * IMG + gx;
        const float* p2 = img2 + ib + (long)gybase * IMG + gx;

        float acc0[G] = {0,0,0,0};
        float acc1[G] = {0,0,0,0};
        float acc2[G] = {0,0,0,0};
        float acc3[G] = {0,0,0,0};
        float acc4[G] = {0,0,0,0};
        #pragma unroll
        for (int j = 0; j < JROWS; j++) {
            int gy = gybase + j;
            bool in = xin & (gy >= 0) & (gy < IMG);
            float av = in ? p1[j * IMG] : 0.f;   // immediate offsets off base reg
            float bv = in ? p2[j * IMG] : 0.f;
            float aa = av * av, bb = bv * bv, ab = av * bv;
            #pragma unroll
            for (int o = 0; o < G; o++) {
                const int d = j - o;
                if (d >= 0 && d < 11) {
                    const float w = wgt(d);      // compile-time const -> FFMA-imm
                    acc0[o] += w * av;
                    acc1[o] += w * bv;
                    acc2[o] += w * aa;
                    acc3[o] += w * bb;
                    acc4[o] += w * ab;
                }
            }
        }
        #pragma unroll
        for (int o = 0; o < G; o++) {
            int row = ybase + o;
            vbuf[(0 * TH + row) * RS + col] = acc0[o];
            vbuf[(1 * TH + row) * RS + col] = acc1[o];
            vbuf[(2 * TH + row) * RS + col] = acc2[o];
            vbuf[(3 * TH + row) * RS + col] = acc3[o];
            vbuf[(4 * TH + row) * RS + col] = acc4[o];
        }
    }
    __syncthreads();

    // ---- stage 2: two statically-shaped slots per thread (fully unrolled) ----
    float lsum = stage2_slot(vbuf, tid);
    if (tid < NSLOTS2 - NTHREADS)           // 224 threads take a second slot
        lsum += stage2_slot(vbuf, tid + NTHREADS);

    // ---- block reduction (9 warps) ----
    #pragma unroll
    for (int off = 16; off > 0; off >>= 1)
        lsum += __shfl_xor_sync(0xffffffff, lsum, off);
    if ((tid & 31) == 0) red[tid >> 5] = lsum;
    __syncthreads();

    // ---- single-kernel finalize: atomic accumulate + last-block writes out ----
    if (tid == 0) {
        float v = 0.f;
        #pragma unroll
        for (int w = 0; w < NWARPS; w++) v += red[w];
        atomicAdd(&g_accum, (double)v);
        __threadfence();
        unsigned int ticket = atomicAdd(&g_count, 1u);
        if (ticket == NBLOCKS - 1) {
            double sfin = atomicAdd(&g_accum, 0.0);   // coherent read of final sum
            out[0] = (float)(1.0 - sfin / NPIX_D);
            g_accum = 0.0;                             // reset for next graph replay
            g_count = 0u;
        }
    }
}

extern "C" void kernel_launch(void* const* d_in, const int* in_sizes, int n_in,
                              void* d_out, int out_size) {
    const float* img1 = (const float*)d_in[0];
    const float* img2 = (const float*)d_in[1];
    float* out = (float*)d_out;

    const size_t smem = (size_t)(5 * TH * RS + NWARPS) * sizeof(float);  // ~44.9 KB
    cudaFuncSetAttribute(ssim_main_kernel,
                         cudaFuncAttributeMaxDynamicSharedMemorySize, (int)smem);

    dim3 grid(IMG / TW, IMG / TH, BATCH);   // 4 x 32 x 32 = 4096 blocks
    ssim_main_kernel<<<grid, NTHREADS, smem>>>(img1, img2, out);
}

// round 14
// speedup vs baseline: 1.8662x; 1.1345x over previous
#include <cuda_runtime.h>

#define IMG 512
#define BATCH 32
#define TW 128
#define TH 16
#define RAD 5
#define RAW_W 138        // TW + 2*RAD columns needed by stage 2
#define RS 140           // vbuf row stride (floats), multiple of 4 for float4 LDS
#define NTHREADS 288
#define NWARPS (NTHREADS / 32)
#define NBLOCKS 4096     // (512/128) * (512/16) * 32
#define NPIX_D 8388608.0
#define G 4              // stage-1 vertical row-group size
#define NSLOTS1 (4 * RAW_W)   // 552 stage-1 slots: 552/288 -> max 2/thread
#define NSLOTS2 (TW * TH / 4) // 512 stage-2 slots: tid and tid+288 (guarded)
#define JROWS (G + 10)        // 14 raw rows feed 4 output rows
#define NPLANES 4             // {conv(a), conv(b), conv(a^2+b^2), conv(ab)}

__device__ double g_accum;          // zero-initialized at module load
__device__ unsigned int g_count;    // zero-initialized at module load

// Normalized 1-D Gaussian, sigma=1.5, K=11; symmetric W[d]=W[10-d]
__device__ __forceinline__ float wgt(int d) {
    const float WH[6] = {0.00102838f, 0.00759876f, 0.03600078f,
                         0.10936070f, 0.21300554f, 0.26601172f};
    return WH[d < 6 ? d : 10 - d];
}

// One stage-2 slot: horizontal 11-tap conv of 4 planes + SSIM for 4 pixels.
__device__ __forceinline__ float stage2_slot(const float* __restrict__ vbuf, int slot) {
    const int xg = slot & 31;               // 32 x-groups * 16 rows
    const int y  = slot >> 5;
    const int x0 = xg * 4;                  // 16B-aligned (RS multiple of 4)
    float res[NPLANES][4];
    #pragma unroll
    for (int q = 0; q < NPLANES; q++) {
        const float* row = vbuf + (q * TH + y) * RS + x0;
        float win[14];
        float4 v0 = *(const float4*)(row);
        float4 v1 = *(const float4*)(row + 4);
        float4 v2 = *(const float4*)(row + 8);
        float2 v3 = *(const float2*)(row + 12);
        win[0] = v0.x;  win[1] = v0.y;  win[2]  = v0.z;  win[3]  = v0.w;
        win[4] = v1.x;  win[5] = v1.y;  win[6]  = v1.z;  win[7]  = v1.w;
        win[8] = v2.x;  win[9] = v2.y;  win[10] = v2.z;  win[11] = v2.w;
        win[12] = v3.x; win[13] = v3.y;
        #pragma unroll
        for (int o = 0; o < 4; o++) {
            float sacc = 0.f;
            #pragma unroll
            for (int d = 0; d < 11; d++) sacc += wgt(d) * win[o + d];
            res[q][o] = sacc;
        }
    }
    float acc = 0.f;
    #pragma unroll
    for (int o = 0; o < 4; o++) {
        float mu1 = res[0][o], mu2 = res[1][o];
        float mu12 = mu1 * mu2;
        float musq = fmaf(mu1, mu1, mu2 * mu2);        // mu1^2 + mu2^2
        float s12  = res[3][o] - mu12;                 // E[ab] - mu1*mu2
        float sigs = res[2][o] - musq;                 // (s1 + s2)
        float num = (2.f * mu12 + 0.0001f) * (2.f * s12 + 0.0009f);
        float den = (musq + 0.0001f) * (sigs + 0.0009f);
        acc += __fdividef(num, den);
    }
    return acc;
}

__global__ __launch_bounds__(NTHREADS, 4)
void ssim_main_kernel(const float* __restrict__ img1, const float* __restrict__ img2,
                      float* __restrict__ out) {
    extern __shared__ float sm[];
    float* vbuf = sm;                       // 4 planes * 16 * 140
    float* red  = sm + NPLANES * TH * RS;   // NWARPS floats

    const int tid = threadIdx.x;
    const int bx0 = blockIdx.x * TW - RAD;
    const int by0 = blockIdx.y * TH - RAD;
    const long ib = (long)blockIdx.z * IMG * IMG;

    // ---- stage 1: vertical 11-tap conv of 4 quantities, direct from global ----
    // 552 slots = 138 columns x 4 row-groups; 288 threads -> at most 2 slots each.
    for (int s = tid; s < NSLOTS1; s += NTHREADS) {
        int grp = s / RAW_W;                // constant division -> mul/shift
        int col = s - grp * RAW_W;          // 0..137
        int ybase = grp * G;
        int gx = bx0 + col;
        int gybase = by0 + ybase;
        const bool xin = (gx >= 0) & (gx < IMG);
        const float* p1 = img1 + ib + (long)gybase * IMG + gx;
        const float* p2 = img2 + ib + (long)gybase * IMG + gx;

        float acc0[G] = {0,0,0,0};
        float acc1[G] = {0,0,0,0};
        float acc2[G] = {0,0,0,0};
        float acc3[G] = {0,0,0,0};
        #pragma unroll
        for (int j = 0; j < JROWS; j++) {
            int gy = gybase + j;
            bool in = xin & (gy >= 0) & (gy < IMG);
            float av = in ? p1[j * IMG] : 0.f;   // immediate offsets off base reg
            float bv = in ? p2[j * IMG] : 0.f;
            float sq = fmaf(bv, bv, av * av);    // a^2 + b^2 folded pre-conv
            float ab = av * bv;
            #pragma unroll
            for (int o = 0; o < G; o++) {
                const int d = j - o;
                if (d >= 0 && d < 11) {
                    const float w = wgt(d);      // compile-time const -> FFMA-imm
                    acc0[o] += w * av;
                    acc1[o] += w * bv;
                    acc2[o] += w * sq;
                    acc3[o] += w * ab;
                }
            }
        }
        #pragma unroll
        for (int o = 0; o < G; o++) {
            int row = ybase + o;
            vbuf[(0 * TH + row) * RS + col] = acc0[o];
            vbuf[(1 * TH + row) * RS + col] = acc1[o];
            vbuf[(2 * TH + row) * RS + col] = acc2[o];
            vbuf[(3 * TH + row) * RS + col] = acc3[o];
        }
    }
    __syncthreads();

    // ---- stage 2: two statically-shaped slots per thread (fully unrolled) ----
    float lsum = stage2_slot(vbuf, tid);
    if (tid < NSLOTS2 - NTHREADS)           // 224 threads take a second slot
        lsum += stage2_slot(vbuf, tid + NTHREADS);

    // ---- block reduction (9 warps) ----
    #pragma unroll
    for (int off = 16; off > 0; off >>= 1)
        lsum += __shfl_xor_sync(0xffffffff, lsum, off);
    if ((tid & 31) == 0) red[tid >> 5] = lsum;
    __syncthreads();

    // ---- single-kernel finalize: atomic accumulate + last-block writes out ----
    if (tid == 0) {
        float v = 0.f;
        #pragma unroll
        for (int w = 0; w < NWARPS; w++) v += red[w];
        atomicAdd(&g_accum, (double)v);
        __threadfence();
        unsigned int ticket = atomicAdd(&g_count, 1u);
        if (ticket == NBLOCKS - 1) {
            double sfin = atomicAdd(&g_accum, 0.0);   // coherent read of final sum
            out[0] = (float)(1.0 - sfin / NPIX_D);
            g_accum = 0.0;                             // reset for next graph replay
            g_count = 0u;
        }
    }
}

extern "C" void kernel_launch(void* const* d_in, const int* in_sizes, int n_in,
                              void* d_out, int out_size) {
    const float* img1 = (const float*)d_in[0];
    const float* img2 = (const float*)d_in[1];
    float* out = (float*)d_out;

    const size_t smem = (size_t)(NPLANES * TH * RS + NWARPS) * sizeof(float); // ~35.9 KB
    cudaFuncSetAttribute(ssim_main_kernel,
                         cudaFuncAttributeMaxDynamicSharedMemorySize, (int)smem);

    dim3 grid(IMG / TW, IMG / TH, BATCH);   // 4 x 32 x 32 = 4096 blocks
    ssim_main_kernel<<<grid, NTHREADS, smem>>>(img1, img2, out);
}